// round 14
// baseline (speedup 1.0000x reference)
#include <cuda_runtime.h>

#define B_ROWS 32768
#define D_IN   200
#define K_SAMP 10
#define TM     64
#define APAD   68
#define NTILES 512            // B_ROWS / TM
#define NBLKS  4096           // B_ROWS / 8
#define MLP_W  148            // mlp worker CTAs
#define GRID_T 304            // 2 per SM (<= 2*152 on GB300)

__device__ float g_logits[(size_t)B_ROWS * D_IN];
__device__ int   g_flag[NTILES];

// smem (floats): XsT[200][68] | H1T[100][68] (L2/L3 in-place) | WS 2 slots of 2240
#define OFF_X  0
#define OFF_H1 (200 * APAD)               // 13600
#define OFF_WS (OFF_H1 + 100 * APAD)      // 20400
#define WSLOT  2240
#define SMEM_FLOATS (OFF_WS + 2 * WSLOT)  // 24880 floats = 99520 B -> 2 CTAs/SM

typedef unsigned long long ull;

__device__ __forceinline__ ull pack2(float lo, float hi) {
    ull r; asm("mov.b64 %0, {%1, %2};" : "=l"(r) : "f"(lo), "f"(hi)); return r;
}
__device__ __forceinline__ ull dup2(float w) {
    ull r; asm("mov.b64 %0, {%1, %1};" : "=l"(r) : "f"(w)); return r;
}
__device__ __forceinline__ void unpack2(ull v, float& lo, float& hi) {
    asm("mov.b64 {%0, %1}, %2;" : "=f"(lo), "=f"(hi) : "l"(v));
}
__device__ __forceinline__ ull fma2(ull a, ull b, ull c) {
    ull d; asm("fma.rn.f32x2 %0, %1, %2, %3;" : "=l"(d) : "l"(a), "l"(b), "l"(c)); return d;
}
__device__ __forceinline__ ull mul2(ull a, ull b) {
    ull d; asm("mul.rn.f32x2 %0, %1, %2;" : "=l"(d) : "l"(a), "l"(b)); return d;
}
__device__ __forceinline__ ull add2(ull a, ull b) {
    ull d; asm("add.rn.f32x2 %0, %1, %2;" : "=l"(d) : "l"(a), "l"(b)); return d;
}
__device__ __forceinline__ float frcp(float x) {
    float r; asm("rcp.approx.f32 %0, %1;" : "=f"(r) : "f"(x)); return r;
}
__device__ __forceinline__ float flg2(float x) {
    float r; asm("lg2.approx.f32 %0, %1;" : "=f"(r) : "f"(x)); return r;
}

// ---- one layer over 64 rows (R13, proven); 8 warps x 8 rows ----
template <int K, int N, int CI, int BK, bool RELU, bool TOGLOBAL>
__device__ __forceinline__ void layer(float* smem, const float* Asm,
                                      const float* __restrict__ Wg,
                                      const float* __restrict__ bg,
                                      float* Hsm, float* __restrict__ Gout,
                                      int tid) {
    static_assert(BK % 2 == 0, "BK even");
    constexpr int NLD = (BK * N + 255) / 256;
    constexpr int NCH = K / BK;
    const int lane = tid & 31;
    const int wy = tid >> 5;

    ull acc[4][CI];
#pragma unroll
    for (int r = 0; r < 4; r++)
#pragma unroll
        for (int c = 0; c < CI; c++) acc[r][c] = 0ull;

    float pf[NLD];
#pragma unroll
    for (int i = 0; i < NLD; i++) {
        int idx = tid + 256 * i;
        if (idx < BK * N) pf[i] = Wg[idx];
    }
    __syncthreads();
    {
        float* ws0 = smem + OFF_WS;
#pragma unroll
        for (int i = 0; i < NLD; i++) {
            int idx = tid + 256 * i;
            if (idx < BK * N) {
                int kk = idx / N, c = idx - kk * N;
                ws0[(kk >> 1) * (2 * N) + 2 * c + (kk & 1)] = pf[i];
            }
        }
    }
    __syncthreads();

    for (int ch = 0; ch < NCH; ch++) {
        const float* cur = smem + OFF_WS + (ch & 1) * WSLOT;
        const bool more = (ch + 1) < NCH;
        if (more) {
            const float* wn = Wg + (size_t)(ch + 1) * BK * N;
#pragma unroll
            for (int i = 0; i < NLD; i++) {
                int idx = tid + 256 * i;
                if (idx < BK * N) pf[i] = wn[idx];
            }
        }
        const float* abase = Asm + ch * BK * APAD + wy * 8;
#pragma unroll
        for (int kk = 0; kk < BK; kk += 2) {
            float2 wv[CI];
#pragma unroll
            for (int c = 0; c < CI; c++)
                wv[c] = *(const float2*)&cur[(kk >> 1) * (2 * N) + 2 * (lane + 32 * c)];
            const float* ar0 = abase + kk * APAD;
            const float* ar1 = abase + (kk + 1) * APAD;
            ulonglong2 a01 = *(const ulonglong2*)ar0;
            ulonglong2 a23 = *(const ulonglong2*)(ar0 + 4);
            ulonglong2 b01 = *(const ulonglong2*)ar1;
            ulonglong2 b23 = *(const ulonglong2*)(ar1 + 4);
#pragma unroll
            for (int c = 0; c < CI; c++) {
                ull w0 = dup2(wv[c].x);
                ull w1 = dup2(wv[c].y);
                acc[0][c] = fma2(a01.x, w0, acc[0][c]);
                acc[1][c] = fma2(a01.y, w0, acc[1][c]);
                acc[2][c] = fma2(a23.x, w0, acc[2][c]);
                acc[3][c] = fma2(a23.y, w0, acc[3][c]);
                acc[0][c] = fma2(b01.x, w1, acc[0][c]);
                acc[1][c] = fma2(b01.y, w1, acc[1][c]);
                acc[2][c] = fma2(b23.x, w1, acc[2][c]);
                acc[3][c] = fma2(b23.y, w1, acc[3][c]);
            }
        }
        if (more) {
            float* nxt = smem + OFF_WS + ((ch + 1) & 1) * WSLOT;
#pragma unroll
            for (int i = 0; i < NLD; i++) {
                int idx = tid + 256 * i;
                if (idx < BK * N) {
                    int kk = idx / N, c = idx - kk * N;
                    nxt[(kk >> 1) * (2 * N) + 2 * c + (kk & 1)] = pf[i];
                }
            }
            __syncthreads();
        }
    }

#pragma unroll
    for (int c = 0; c < CI; c++) {
        int col = lane + 32 * c;
        if (col < N) {
            float bv = bg[col];
#pragma unroll
            for (int r = 0; r < 4; r++) {
                float lo, hi;
                unpack2(acc[r][c], lo, hi);
                lo += bv; hi += bv;
                if (RELU) { lo = fmaxf(lo, 0.0f); hi = fmaxf(hi, 0.0f); }
                int row = wy * 8 + 2 * r;
                if (TOGLOBAL) {
                    Gout[(size_t)row * N + col] = lo;
                    Gout[(size_t)(row + 1) * N + col] = hi;
                } else {
                    *(float2*)&Hsm[col * APAD + row] = make_float2(lo, hi);
                }
            }
        }
    }
}

// ---- sampler helpers (R12, proven) ----
__device__ __forceinline__ void load8(float* dst, const float* src, bool act) {
    if (act) {
        float4 a = *(const float4*)src;
        float4 b = *(const float4*)(src + 4);
        dst[0] = a.x; dst[1] = a.y; dst[2] = a.z; dst[3] = a.w;
        dst[4] = b.x; dst[5] = b.y; dst[6] = b.z; dst[7] = b.w;
    } else {
#pragma unroll
        for (int i = 0; i < 8; i++) dst[i] = 0.5f;
    }
}

__device__ __forceinline__ float gumbel8(float* u, const ull* Epk,
                                         ull C1, ull C2, ull C3, ull M1) {
    constexpr float EPSF = 1.1920929e-07f;
    ull sacc = 0ull;
#pragma unroll
    for (int j = 0; j < 4; j++) {
        float u0 = fmaxf(u[2 * j], EPSF);
        float u1 = fmaxf(u[2 * j + 1], EPSF);
        float l0 = flg2(u0);
        float l1 = flg2(u1);
        ull upk = pack2(u0, u1);
        ull xm = add2(upk, M1);
        ull q = fma2(xm, fma2(xm, C3, C2), C1);
        ull pp = mul2(xm, q);
        float p0, p1;
        unpack2(pp, p0, p1);
        float t0 = (u0 > 0.99f) ? p0 : l0;
        float t1 = (u1 > 0.99f) ? p1 : l1;
        ull tt = pack2(t0, t1);
        ull t2 = mul2(tt, tt);
        float s0, s1;
        unpack2(t2, s0, s1);
        ull rr = pack2(frcp(s0), frcp(s1));
        ull w = mul2(Epk[j], rr);
        float w0, w1;
        unpack2(w, w0, w1);
        u[2 * j] = w0; u[2 * j + 1] = w1;
        sacc = add2(sacc, w);
    }
    float sl, sh;
    unpack2(sacc, sl, sh);
    return sl + sh;
}

__device__ __forceinline__ void sample_rowblock(
    int b, int lane,
    const float* __restrict__ x, const float* __restrict__ uniform,
    const float* __restrict__ logits,
    const float* __restrict__ wo, const float* __restrict__ bo,
    float* __restrict__ preds, float* __restrict__ samples) {
    const bool act = lane < 25;
    const int d0 = 8 * lane;

    const ull C1 = pack2(1.44269504f, 1.44269504f);
    const ull C2 = pack2(-0.72134752f, -0.72134752f);
    const ull C3 = pack2(0.48089835f, 0.48089835f);
    const ull M1 = pack2(-1.0f, -1.0f);

    ull Epk[4];
    float smp[8];
    {
        float lg[8];
        if (act) load8(lg, &logits[(size_t)b * D_IN + d0], true);
        else {
#pragma unroll
            for (int i = 0; i < 8; i++) lg[i] = -1e30f;
        }
        float m = lg[0];
#pragma unroll
        for (int i = 1; i < 8; i++) m = fmaxf(m, lg[i]);
#pragma unroll
        for (int off = 16; off > 0; off >>= 1)
            m = fmaxf(m, __shfl_xor_sync(0xffffffffu, m, off));
#pragma unroll
        for (int j = 0; j < 4; j++) {
            float e0 = act ? __expf(2.0f * (lg[2 * j] - m)) : 0.0f;
            float e1 = act ? __expf(2.0f * (lg[2 * j + 1] - m)) : 0.0f;
            Epk[j] = pack2(e0, e1);
        }
#pragma unroll
        for (int i = 0; i < 8; i++) smp[i] = 0.0f;
    }

    const float* up = uniform + (size_t)b * (K_SAMP * D_IN) + d0;
    float ua[8], ub[8];
    load8(ua, up, act);
    load8(ub, up + D_IN, act);

#pragma unroll
    for (int kp = 0; kp < K_SAMP / 2; kp++) {
        float na[8], nb[8];
        if (kp < K_SAMP / 2 - 1) {
            load8(na, up + (2 * kp + 2) * D_IN, act);
            load8(nb, up + (2 * kp + 3) * D_IN, act);
        }
        float sA = gumbel8(ua, Epk, C1, C2, C3, M1);
        float sB = gumbel8(ub, Epk, C1, C2, C3, M1);
#pragma unroll
        for (int off = 16; off > 0; off >>= 1) {
            sA += __shfl_xor_sync(0xffffffffu, sA, off);
            sB += __shfl_xor_sync(0xffffffffu, sB, off);
        }
        float ia = frcp(sA), ib = frcp(sB);
#pragma unroll
        for (int i = 0; i < 8; i++) {
            smp[i] = fmaxf(smp[i], ua[i] * ia);
            smp[i] = fmaxf(smp[i], ub[i] * ib);
        }
        if (kp < K_SAMP / 2 - 1) {
#pragma unroll
            for (int i = 0; i < 8; i++) { ua[i] = na[i]; ub[i] = nb[i]; }
        }
    }

    if (act) {
        *(float4*)&samples[(size_t)b * D_IN + d0] =
            make_float4(smp[0], smp[1], smp[2], smp[3]);
        *(float4*)&samples[(size_t)b * D_IN + d0 + 4] =
            make_float4(smp[4], smp[5], smp[6], smp[7]);
    }

    float p0 = 0.0f, p1 = 0.0f;
    if (act) {
        float xv[8];
        load8(xv, &x[(size_t)b * D_IN + d0], true);
#pragma unroll
        for (int i = 0; i < 8; i += 2) {
            float4 w4 = *(const float4*)&wo[(d0 + i) * 2];
            float a0 = xv[i] * smp[i], a1 = xv[i + 1] * smp[i + 1];
            p0 += a0 * w4.x + a1 * w4.z;
            p1 += a0 * w4.y + a1 * w4.w;
        }
    }
#pragma unroll
    for (int off = 16; off > 0; off >>= 1) {
        p0 += __shfl_xor_sync(0xffffffffu, p0, off);
        p1 += __shfl_xor_sync(0xffffffffu, p1, off);
    }
    if (lane == 0) {
        p0 += bo[0]; p1 += bo[1];
        float mm = fmaxf(p0, p1);
        float e0 = __expf(p0 - mm), e1 = __expf(p1 - mm);
        float is = 1.0f / (e0 + e1);
        preds[(size_t)b * 2 + 0] = e0 * is;
        preds[(size_t)b * 2 + 1] = e1 * is;
    }
}

// ---- merged persistent heterogeneous kernel ----
__global__ __launch_bounds__(256, 2) void fused_kernel(
    const float* __restrict__ x, const float* __restrict__ uniform,
    const float* __restrict__ w1, const float* __restrict__ b1,
    const float* __restrict__ w2, const float* __restrict__ b2,
    const float* __restrict__ wl, const float* __restrict__ bl,
    const float* __restrict__ wo, const float* __restrict__ bo,
    float* __restrict__ out) {
    extern __shared__ float smem[];
    const int tid = threadIdx.x;
    float* lgts = g_logits;

    if (blockIdx.x < MLP_W) {
        // ---- MLP worker: tiles bid, bid+148, ... ----
        for (int tile = blockIdx.x; tile < NTILES; tile += MLP_W) {
            const int rowBase = tile * TM;
            {
                const float4* xb = (const float4*)(x + (size_t)rowBase * D_IN);
                for (int it = tid; it < 64 * 50; it += 256) {
                    int q = it >> 6, row = it & 63;
                    float4 v = xb[row * 50 + q];
                    float* p = smem + OFF_X + (4 * q) * APAD + row;
                    p[0] = v.x; p[APAD] = v.y; p[2 * APAD] = v.z; p[3 * APAD] = v.w;
                }
            }
            layer<200, 100, 4, 10, true, false>(smem, smem + OFF_X, w1, b1,
                                                smem + OFF_H1, nullptr, tid);
            layer<100, 100, 4, 10, true, false>(smem, smem + OFF_H1, w2, b2,
                                                smem + OFF_H1, nullptr, tid);
            layer<100, 200, 7, 10, false, true>(smem, smem + OFF_H1, wl, bl, nullptr,
                                                lgts + (size_t)rowBase * D_IN, tid);
            __syncthreads();            // all warps' logits STG issued
            if (tid == 0) {
                __threadfence();        // release
                ((volatile int*)g_flag)[tile] = 1;
            }
            // next tile's x-staging (OFF_X) is disjoint from any lingering reads
        }
    } else {
        // ---- sampler worker: row-blocks of 8, gated on tile flags ----
        const int s = blockIdx.x - MLP_W;
        const int lane = tid & 31;
        const int wy = tid >> 5;
        float* preds = out;
        float* samples = out + (size_t)B_ROWS * 2;
        for (int j = s; j < NBLKS; j += (GRID_T - MLP_W)) {
            if (tid == 0) {
                while (((volatile int*)g_flag)[j >> 3] == 0) { __nanosleep(128); }
                __threadfence();        // acquire
            }
            __syncthreads();
            sample_rowblock(8 * j + wy, lane, x, uniform, lgts, wo, bo, preds, samples);
            __syncthreads();            // keep warps loosely together for flag reuse
        }
    }
}

extern "C" void kernel_launch(void* const* d_in, const int* in_sizes, int n_in,
                              void* d_out, int out_size) {
    const float* x  = (const float*)d_in[0];
    const float* un = (const float*)d_in[1];
    const float* w1 = (const float*)d_in[2];
    const float* b1 = (const float*)d_in[3];
    const float* w2 = (const float*)d_in[4];
    const float* b2 = (const float*)d_in[5];
    const float* wl = (const float*)d_in[6];
    const float* bl = (const float*)d_in[7];
    const float* wo = (const float*)d_in[8];
    const float* bo = (const float*)d_in[9];
    float* out = (float*)d_out;

    int* flg;
    cudaGetSymbolAddress((void**)&flg, g_flag);
    cudaMemsetAsync(flg, 0, NTILES * sizeof(int));

    const int smem_bytes = SMEM_FLOATS * (int)sizeof(float);  // 99520
    cudaFuncSetAttribute(fused_kernel, cudaFuncAttributeMaxDynamicSharedMemorySize, smem_bytes);

    fused_kernel<<<GRID_T, 256, smem_bytes>>>(x, un, w1, b1, w2, b2, wl, bl, wo, bo, out);
}

// round 16
// speedup vs baseline: 1.5435x; 1.5435x over previous
#include <cuda_runtime.h>
#include <cstdint>

#define B_ROWS 32768
#define D_IN   200
#define K_SAMP 10
#define TM     64
#define APAD   68

__device__ float g_logits[(size_t)B_ROWS * D_IN];

// ---- MLP smem (floats): XsT[200][68] | H1T[100][68] (L2/L3 in-place) | WS dbl-buffer
#define OFF_X  0
#define OFF_H1 (200 * APAD)            // 13600
#define OFF_WS (OFF_H1 + 100 * APAD)   // 20400
#define WSLOT  2560                    // per-slot floats: max(128*20, 224*10)
#define SMEM_FLOATS (OFF_WS + 2 * WSLOT)  // 25520 floats = 102080 B

typedef unsigned long long ull;

__device__ __forceinline__ ull pack2(float lo, float hi) {
    ull r; asm("mov.b64 %0, {%1, %2};" : "=l"(r) : "f"(lo), "f"(hi)); return r;
}
__device__ __forceinline__ ull dup2(float w) {
    ull r; asm("mov.b64 %0, {%1, %1};" : "=l"(r) : "f"(w)); return r;
}
__device__ __forceinline__ void unpack2(ull v, float& lo, float& hi) {
    asm("mov.b64 {%0, %1}, %2;" : "=f"(lo), "=f"(hi) : "l"(v));
}
__device__ __forceinline__ ull fma2(ull a, ull b, ull c) {
    ull d; asm("fma.rn.f32x2 %0, %1, %2, %3;" : "=l"(d) : "l"(a), "l"(b), "l"(c)); return d;
}
__device__ __forceinline__ ull mul2(ull a, ull b) {
    ull d; asm("mul.rn.f32x2 %0, %1, %2;" : "=l"(d) : "l"(a), "l"(b)); return d;
}
__device__ __forceinline__ ull add2(ull a, ull b) {
    ull d; asm("add.rn.f32x2 %0, %1, %2;" : "=l"(d) : "l"(a), "l"(b)); return d;
}
__device__ __forceinline__ float frcp(float x) {
    float r; asm("rcp.approx.f32 %0, %1;" : "=f"(r) : "f"(x)); return r;
}
__device__ __forceinline__ float flg2(float x) {
    float r; asm("lg2.approx.f32 %0, %1;" : "=f"(r) : "f"(x)); return r;
}

// ================== MLP (R8 champion, verbatim) ==================
template <int K, int N, int CI, int BK, bool RELU, bool TOGLOBAL>
__device__ __forceinline__ void layer(float* smem, const float* Asm,
                                      const float* __restrict__ Wg,
                                      const float* __restrict__ bg,
                                      float* Hsm, float* __restrict__ Gout,
                                      int tid) {
    constexpr int KSTEP = (BK % 4 == 0) ? 4 : 2;
    constexpr int NLD = (BK * N + 255) / 256;
    constexpr int NCH = K / BK;
    const int lane = tid & 31;
    const int wy = tid >> 5;   // rows [8wy, 8wy+8)

    ull acc[4][CI];
#pragma unroll
    for (int r = 0; r < 4; r++)
#pragma unroll
        for (int c = 0; c < CI; c++) acc[r][c] = 0ull;

    float pf[NLD];
#pragma unroll
    for (int i = 0; i < NLD; i++) {
        int idx = tid + 256 * i;
        if (idx < BK * N) pf[i] = Wg[idx];
    }
    __syncthreads();
    {
        float* ws0 = smem + OFF_WS;
#pragma unroll
        for (int i = 0; i < NLD; i++) {
            int idx = tid + 256 * i;
            if (idx < BK * N) { int kk = idx / N, c = idx - kk * N; ws0[c * BK + kk] = pf[i]; }
        }
    }
    __syncthreads();

    for (int ch = 0; ch < NCH; ch++) {
        const float* cur = smem + OFF_WS + (ch & 1) * WSLOT;
        const bool more = (ch + 1) < NCH;
        if (more) {
            const float* wn = Wg + (size_t)(ch + 1) * BK * N;
#pragma unroll
            for (int i = 0; i < NLD; i++) {
                int idx = tid + 256 * i;
                if (idx < BK * N) pf[i] = wn[idx];
            }
        }
        const float* abase = Asm + ch * BK * APAD + wy * 8;
#pragma unroll
        for (int kk = 0; kk < BK; kk += KSTEP) {
            float wv[CI][KSTEP];
#pragma unroll
            for (int c = 0; c < CI; c++) {
                const float* wp_ = &cur[(lane + 32 * c) * BK + kk];
                if (KSTEP == 4) {
                    float4 v = *(const float4*)wp_;
                    wv[c][0] = v.x; wv[c][1] = v.y; wv[c][2] = v.z; wv[c][3] = v.w;
                } else {
                    float2 v = *(const float2*)wp_;
                    wv[c][0] = v.x; wv[c][1] = v.y;
                }
            }
#pragma unroll
            for (int j = 0; j < KSTEP; j++) {
                const float* arow = abase + (kk + j) * APAD;
                ulonglong2 a01 = *(const ulonglong2*)arow;
                ulonglong2 a23 = *(const ulonglong2*)(arow + 4);
#pragma unroll
                for (int c = 0; c < CI; c++) {
                    ull wp = dup2(wv[c][j]);
                    acc[0][c] = fma2(a01.x, wp, acc[0][c]);
                    acc[1][c] = fma2(a01.y, wp, acc[1][c]);
                    acc[2][c] = fma2(a23.x, wp, acc[2][c]);
                    acc[3][c] = fma2(a23.y, wp, acc[3][c]);
                }
            }
        }
        if (more) {
            float* nxt = smem + OFF_WS + ((ch + 1) & 1) * WSLOT;
#pragma unroll
            for (int i = 0; i < NLD; i++) {
                int idx = tid + 256 * i;
                if (idx < BK * N) { int kk = idx / N, c = idx - kk * N; nxt[c * BK + kk] = pf[i]; }
            }
            __syncthreads();
        }
    }

#pragma unroll
    for (int c = 0; c < CI; c++) {
        int col = lane + 32 * c;
        if (col < N) {
            float bv = bg[col];
#pragma unroll
            for (int r = 0; r < 4; r++) {
                float lo, hi;
                unpack2(acc[r][c], lo, hi);
                lo += bv; hi += bv;
                if (RELU) { lo = fmaxf(lo, 0.0f); hi = fmaxf(hi, 0.0f); }
                int row = wy * 8 + 2 * r;
                if (TOGLOBAL) {
                    Gout[(size_t)row * N + col] = lo;
                    Gout[(size_t)(row + 1) * N + col] = hi;
                } else {
                    *(float2*)&Hsm[col * APAD + row] = make_float2(lo, hi);
                }
            }
        }
    }
}

__global__ __launch_bounds__(256, 2) void mlp_kernel(
    const float* __restrict__ x,
    const float* __restrict__ w1, const float* __restrict__ b1,
    const float* __restrict__ w2, const float* __restrict__ b2,
    const float* __restrict__ wl, const float* __restrict__ bl,
    float* __restrict__ logits) {
    extern __shared__ float smem[];
    const int tid = threadIdx.x;
    const int rowBase = blockIdx.x * TM;

    {
        const float4* xb = (const float4*)(x + (size_t)rowBase * D_IN);
        for (int it = tid; it < 64 * 50; it += 256) {
            int q = it >> 6, row = it & 63;
            float4 v = xb[row * 50 + q];
            float* p = smem + OFF_X + (4 * q) * APAD + row;
            p[0] = v.x; p[APAD] = v.y; p[2 * APAD] = v.z; p[3 * APAD] = v.w;
        }
    }
    layer<200, 100, 4, 20, true, false>(smem, smem + OFF_X, w1, b1, smem + OFF_H1, nullptr, tid);
    layer<100, 100, 4, 20, true, false>(smem, smem + OFF_H1, w2, b2, smem + OFF_H1, nullptr, tid);
    layer<100, 200, 7, 10, false, true>(smem, smem + OFF_H1, wl, bl, nullptr,
                                        logits + (size_t)rowBase * D_IN, tid);
}

// ================== sampler: cp.async 3-stage SMEM pipeline ==================
#define SROWS 8                 // rows per CTA (1 per warp)
#define NKP   5                 // k-pairs
#define NSTG  3                 // pipeline stages
#define STAGE_F (SROWS * 400)   // floats per stage (8 rows x 2k x 200)

__device__ __forceinline__ void cp_async16(unsigned saddr, const float* gptr) {
    asm volatile("cp.async.cg.shared.global [%0], [%1], 16;" :: "r"(saddr), "l"(gptr));
}
__device__ __forceinline__ void cp_commit() {
    asm volatile("cp.async.commit_group;" ::: "memory");
}
template <int N>
__device__ __forceinline__ void cp_wait() {
    asm volatile("cp.async.wait_group %0;" :: "n"(N) : "memory");
}

__device__ __forceinline__ float gumbel8(float* u, const ull* Epk,
                                         ull C1, ull C2, ull C3, ull M1) {
    constexpr float EPSF = 1.1920929e-07f;
    ull sacc = 0ull;
#pragma unroll
    for (int j = 0; j < 4; j++) {
        float u0 = fmaxf(u[2 * j], EPSF);
        float u1 = fmaxf(u[2 * j + 1], EPSF);
        float l0 = flg2(u0);
        float l1 = flg2(u1);
        ull upk = pack2(u0, u1);
        ull xm = add2(upk, M1);                    // u-1 (exact near 1)
        ull q = fma2(xm, fma2(xm, C3, C2), C1);
        ull pp = mul2(xm, q);                      // accurate log2(1+xm)
        float p0, p1;
        unpack2(pp, p0, p1);
        float t0 = (u0 > 0.99f) ? p0 : l0;
        float t1 = (u1 > 0.99f) ? p1 : l1;
        ull tt = pack2(t0, t1);
        ull t2 = mul2(tt, tt);
        float s0, s1;
        unpack2(t2, s0, s1);
        ull rr = pack2(frcp(s0), frcp(s1));
        ull w = mul2(Epk[j], rr);                  // E / lg2(u)^2
        float w0, w1;
        unpack2(w, w0, w1);
        u[2 * j] = w0; u[2 * j + 1] = w1;
        sacc = add2(sacc, w);
    }
    float sl, sh;
    unpack2(sacc, sl, sh);
    return sl + sh;
}

__device__ __forceinline__ void lds8(float* dst, const float* s, bool act) {
    if (act) {
        float4 a = *(const float4*)s;
        float4 b = *(const float4*)(s + 4);
        dst[0] = a.x; dst[1] = a.y; dst[2] = a.z; dst[3] = a.w;
        dst[4] = b.x; dst[5] = b.y; dst[6] = b.z; dst[7] = b.w;
    } else {
#pragma unroll
        for (int i = 0; i < 8; i++) dst[i] = 0.5f;
    }
}

__global__ __launch_bounds__(256, 4) void sample_kernel(
    const float* __restrict__ x, const float* __restrict__ uniform,
    const float* __restrict__ logits,
    const float* __restrict__ wo, const float* __restrict__ bo,
    float* __restrict__ preds, float* __restrict__ samples) {
    __shared__ float su[NSTG][STAGE_F];   // 38400 B static
    const int tid = threadIdx.x;
    const int lane = tid & 31;
    const int wy = tid >> 5;
    const int b = blockIdx.x * SROWS + wy;
    const bool act = lane < 25;
    const int d0 = 8 * lane;

    const float* grow = uniform + (size_t)b * (K_SAMP * D_IN);
    unsigned srow;  // smem byte addr of my row in stage 0
    {
        unsigned base = (unsigned)__cvta_generic_to_shared(&su[0][0]);
        srow = base + (unsigned)(wy * 400) * 4u;
    }
    const unsigned stage_bytes = STAGE_F * 4u;

    // issue stage s holding k-pair kp: each warp loads its own row's 100 float4
    auto issue = [&](int kp, int s) {
#pragma unroll
        for (int q0 = 0; q0 < 4; q0++) {
            int q = lane + 32 * q0;
            if (q < 100)
                cp_async16(srow + (unsigned)s * stage_bytes + (unsigned)q * 16u,
                           grow + kp * 400 + q * 4);
        }
    };

    // prologue: fill pipeline
    issue(0, 0); cp_commit();
    issue(1, 1); cp_commit();
    issue(2, 2); cp_commit();

    const ull C1 = pack2(1.44269504f, 1.44269504f);
    const ull C2 = pack2(-0.72134752f, -0.72134752f);
    const ull C3 = pack2(0.48089835f, 0.48089835f);
    const ull M1 = pack2(-1.0f, -1.0f);

    ull Epk[4];
    float smp[8];
    {
        float lg[8];
        if (act) {
            const float* lp = &logits[(size_t)b * D_IN + d0];
            float4 a = *(const float4*)lp;
            float4 c = *(const float4*)(lp + 4);
            lg[0] = a.x; lg[1] = a.y; lg[2] = a.z; lg[3] = a.w;
            lg[4] = c.x; lg[5] = c.y; lg[6] = c.z; lg[7] = c.w;
        } else {
#pragma unroll
            for (int i = 0; i < 8; i++) lg[i] = -1e30f;
        }
        float m = lg[0];
#pragma unroll
        for (int i = 1; i < 8; i++) m = fmaxf(m, lg[i]);
#pragma unroll
        for (int off = 16; off > 0; off >>= 1)
            m = fmaxf(m, __shfl_xor_sync(0xffffffffu, m, off));
#pragma unroll
        for (int j = 0; j < 4; j++) {
            float e0 = act ? __expf(2.0f * (lg[2 * j] - m)) : 0.0f;
            float e1 = act ? __expf(2.0f * (lg[2 * j + 1] - m)) : 0.0f;
            Epk[j] = pack2(e0, e1);
        }
#pragma unroll
        for (int i = 0; i < 8; i++) smp[i] = 0.0f;
    }

#pragma unroll
    for (int kp = 0; kp < NKP; kp++) {
        cp_wait<2>();          // stage kp landed (per-thread)
        __syncthreads();       // visible CTA-wide
        const float* srd = &su[kp % NSTG][wy * 400];
        float ua[8], ub[8];
        lds8(ua, srd + d0, act);
        lds8(ub, srd + 200 + d0, act);

        float sA = gumbel8(ua, Epk, C1, C2, C3, M1);
        float sB = gumbel8(ub, Epk, C1, C2, C3, M1);
#pragma unroll
        for (int off = 16; off > 0; off >>= 1) {
            sA += __shfl_xor_sync(0xffffffffu, sA, off);
            sB += __shfl_xor_sync(0xffffffffu, sB, off);
        }
        float ia = frcp(sA), ib = frcp(sB);
#pragma unroll
        for (int i = 0; i < 8; i++) {
            smp[i] = fmaxf(smp[i], ua[i] * ia);
            smp[i] = fmaxf(smp[i], ub[i] * ib);
        }

        __syncthreads();       // all warps done reading stage kp%3
        if (kp + 3 < NKP) issue(kp + 3, (kp + 3) % NSTG);
        cp_commit();           // uniform (possibly empty) group
    }

    if (act) {
        *(float4*)&samples[(size_t)b * D_IN + d0] =
            make_float4(smp[0], smp[1], smp[2], smp[3]);
        *(float4*)&samples[(size_t)b * D_IN + d0 + 4] =
            make_float4(smp[4], smp[5], smp[6], smp[7]);
    }

    float p0 = 0.0f, p1 = 0.0f;
    if (act) {
        const float* xp = &x[(size_t)b * D_IN + d0];
        float4 a = *(const float4*)xp;
        float4 c = *(const float4*)(xp + 4);
        float xv[8] = {a.x, a.y, a.z, a.w, c.x, c.y, c.z, c.w};
#pragma unroll
        for (int i = 0; i < 8; i += 2) {
            float4 w4 = *(const float4*)&wo[(d0 + i) * 2];
            float a0 = xv[i] * smp[i], a1 = xv[i + 1] * smp[i + 1];
            p0 += a0 * w4.x + a1 * w4.z;
            p1 += a0 * w4.y + a1 * w4.w;
        }
    }
#pragma unroll
    for (int off = 16; off > 0; off >>= 1) {
        p0 += __shfl_xor_sync(0xffffffffu, p0, off);
        p1 += __shfl_xor_sync(0xffffffffu, p1, off);
    }
    if (lane == 0) {
        p0 += bo[0]; p1 += bo[1];
        float mm = fmaxf(p0, p1);
        float e0 = __expf(p0 - mm), e1 = __expf(p1 - mm);
        float is = 1.0f / (e0 + e1);
        preds[(size_t)b * 2 + 0] = e0 * is;
        preds[(size_t)b * 2 + 1] = e1 * is;
    }
}

extern "C" void kernel_launch(void* const* d_in, const int* in_sizes, int n_in,
                              void* d_out, int out_size) {
    const float* x  = (const float*)d_in[0];
    const float* un = (const float*)d_in[1];
    const float* w1 = (const float*)d_in[2];
    const float* b1 = (const float*)d_in[3];
    const float* w2 = (const float*)d_in[4];
    const float* b2 = (const float*)d_in[5];
    const float* wl = (const float*)d_in[6];
    const float* bl = (const float*)d_in[7];
    const float* wo = (const float*)d_in[8];
    const float* bo = (const float*)d_in[9];
    float* out = (float*)d_out;

    float* lgts;
    cudaGetSymbolAddress((void**)&lgts, g_logits);

    const int smem_bytes = SMEM_FLOATS * (int)sizeof(float);  // 102080
    cudaFuncSetAttribute(mlp_kernel, cudaFuncAttributeMaxDynamicSharedMemorySize, smem_bytes);

    mlp_kernel<<<B_ROWS / TM, 256, smem_bytes>>>(x, w1, b1, w2, b2, wl, bl, lgts);
    sample_kernel<<<B_ROWS / SROWS, 256>>>(x, un, lgts, wo, bo,
                                           out, out + (size_t)B_ROWS * 2);
}

// round 17
// speedup vs baseline: 1.5792x; 1.0231x over previous
#include <cuda_runtime.h>
#include <cstdint>

#define B_ROWS 32768
#define D_IN   200
#define K_SAMP 10
#define TM     64
#define APAD   68
#define NTILES 512
#define MLP_GRID 304   // 2 CTAs/SM x 152 SMs, all resident

__device__ float g_logits[(size_t)B_ROWS * D_IN];
__device__ unsigned g_ctr;

// smem (floats): XsT[200][68] | H1T[100][68] (L2/L3 in-place) | WS dbl-buffer | tile slot
#define OFF_X  0
#define OFF_H1 (200 * APAD)            // 13600
#define OFF_WS (OFF_H1 + 100 * APAD)   // 20400
#define WSLOT  2560
#define OFF_TILE (OFF_WS + 2 * WSLOT)  // 25520
#define SMEM_FLOATS (OFF_TILE + 4)     // 25524 floats = 102096 B -> 2 CTAs/SM

typedef unsigned long long ull;

__device__ __forceinline__ ull pack2(float lo, float hi) {
    ull r; asm("mov.b64 %0, {%1, %2};" : "=l"(r) : "f"(lo), "f"(hi)); return r;
}
__device__ __forceinline__ ull dup2(float w) {
    ull r; asm("mov.b64 %0, {%1, %1};" : "=l"(r) : "f"(w)); return r;
}
__device__ __forceinline__ void unpack2(ull v, float& lo, float& hi) {
    asm("mov.b64 {%0, %1}, %2;" : "=f"(lo), "=f"(hi) : "l"(v));
}
__device__ __forceinline__ ull fma2(ull a, ull b, ull c) {
    ull d; asm("fma.rn.f32x2 %0, %1, %2, %3;" : "=l"(d) : "l"(a), "l"(b), "l"(c)); return d;
}
__device__ __forceinline__ ull mul2(ull a, ull b) {
    ull d; asm("mul.rn.f32x2 %0, %1, %2;" : "=l"(d) : "l"(a), "l"(b)); return d;
}
__device__ __forceinline__ ull add2(ull a, ull b) {
    ull d; asm("add.rn.f32x2 %0, %1, %2;" : "=l"(d) : "l"(a), "l"(b)); return d;
}
__device__ __forceinline__ float frcp(float x) {
    float r; asm("rcp.approx.f32 %0, %1;" : "=f"(r) : "f"(x)); return r;
}
__device__ __forceinline__ float flg2(float x) {
    float r; asm("lg2.approx.f32 %0, %1;" : "=f"(r) : "f"(x)); return r;
}

// ================== MLP layer (R8 champion, verbatim) ==================
template <int K, int N, int CI, int BK, bool RELU, bool TOGLOBAL>
__device__ __forceinline__ void layer(float* smem, const float* Asm,
                                      const float* __restrict__ Wg,
                                      const float* __restrict__ bg,
                                      float* Hsm, float* __restrict__ Gout,
                                      int tid) {
    constexpr int KSTEP = (BK % 4 == 0) ? 4 : 2;
    constexpr int NLD = (BK * N + 255) / 256;
    constexpr int NCH = K / BK;
    const int lane = tid & 31;
    const int wy = tid >> 5;   // rows [8wy, 8wy+8)

    ull acc[4][CI];
#pragma unroll
    for (int r = 0; r < 4; r++)
#pragma unroll
        for (int c = 0; c < CI; c++) acc[r][c] = 0ull;

    float pf[NLD];
#pragma unroll
    for (int i = 0; i < NLD; i++) {
        int idx = tid + 256 * i;
        if (idx < BK * N) pf[i] = Wg[idx];
    }
    __syncthreads();
    {
        float* ws0 = smem + OFF_WS;
#pragma unroll
        for (int i = 0; i < NLD; i++) {
            int idx = tid + 256 * i;
            if (idx < BK * N) { int kk = idx / N, c = idx - kk * N; ws0[c * BK + kk] = pf[i]; }
        }
    }
    __syncthreads();

    for (int ch = 0; ch < NCH; ch++) {
        const float* cur = smem + OFF_WS + (ch & 1) * WSLOT;
        const bool more = (ch + 1) < NCH;
        if (more) {
            const float* wn = Wg + (size_t)(ch + 1) * BK * N;
#pragma unroll
            for (int i = 0; i < NLD; i++) {
                int idx = tid + 256 * i;
                if (idx < BK * N) pf[i] = wn[idx];
            }
        }
        const float* abase = Asm + ch * BK * APAD + wy * 8;
#pragma unroll
        for (int kk = 0; kk < BK; kk += KSTEP) {
            float wv[CI][KSTEP];
#pragma unroll
            for (int c = 0; c < CI; c++) {
                const float* wp_ = &cur[(lane + 32 * c) * BK + kk];
                if (KSTEP == 4) {
                    float4 v = *(const float4*)wp_;
                    wv[c][0] = v.x; wv[c][1] = v.y; wv[c][2] = v.z; wv[c][3] = v.w;
                } else {
                    float2 v = *(const float2*)wp_;
                    wv[c][0] = v.x; wv[c][1] = v.y;
                }
            }
#pragma unroll
            for (int j = 0; j < KSTEP; j++) {
                const float* arow = abase + (kk + j) * APAD;
                ulonglong2 a01 = *(const ulonglong2*)arow;
                ulonglong2 a23 = *(const ulonglong2*)(arow + 4);
#pragma unroll
                for (int c = 0; c < CI; c++) {
                    ull wp = dup2(wv[c][j]);
                    acc[0][c] = fma2(a01.x, wp, acc[0][c]);
                    acc[1][c] = fma2(a01.y, wp, acc[1][c]);
                    acc[2][c] = fma2(a23.x, wp, acc[2][c]);
                    acc[3][c] = fma2(a23.y, wp, acc[3][c]);
                }
            }
        }
        if (more) {
            float* nxt = smem + OFF_WS + ((ch + 1) & 1) * WSLOT;
#pragma unroll
            for (int i = 0; i < NLD; i++) {
                int idx = tid + 256 * i;
                if (idx < BK * N) { int kk = idx / N, c = idx - kk * N; nxt[c * BK + kk] = pf[i]; }
            }
            __syncthreads();
        }
    }

#pragma unroll
    for (int c = 0; c < CI; c++) {
        int col = lane + 32 * c;
        if (col < N) {
            float bv = bg[col];
#pragma unroll
            for (int r = 0; r < 4; r++) {
                float lo, hi;
                unpack2(acc[r][c], lo, hi);
                lo += bv; hi += bv;
                if (RELU) { lo = fmaxf(lo, 0.0f); hi = fmaxf(hi, 0.0f); }
                int row = wy * 8 + 2 * r;
                if (TOGLOBAL) {
                    Gout[(size_t)row * N + col] = lo;
                    Gout[(size_t)(row + 1) * N + col] = hi;
                } else {
                    *(float2*)&Hsm[col * APAD + row] = make_float2(lo, hi);
                }
            }
        }
    }
}

// persistent work-stealing MLP: 304 resident CTAs drain 512 tiles
__global__ __launch_bounds__(256, 2) void mlp_kernel(
    const float* __restrict__ x,
    const float* __restrict__ w1, const float* __restrict__ b1,
    const float* __restrict__ w2, const float* __restrict__ b2,
    const float* __restrict__ wl, const float* __restrict__ bl,
    float* __restrict__ logits) {
    extern __shared__ float smem[];
    const int tid = threadIdx.x;
    int* s_tile = (int*)(smem + OFF_TILE);

    for (;;) {
        if (tid == 0) *s_tile = (int)atomicAdd(&g_ctr, 1u);
        __syncthreads();
        const int tile = *s_tile;
        if (tile >= NTILES) break;
        const int rowBase = tile * TM;

        // stage x transposed: XsT[k][row] (disjoint from WS/H1T: safe vs lagging warps)
        {
            const float4* xb = (const float4*)(x + (size_t)rowBase * D_IN);
            for (int it = tid; it < 64 * 50; it += 256) {
                int q = it >> 6, row = it & 63;
                float4 v = xb[row * 50 + q];
                float* p = smem + OFF_X + (4 * q) * APAD + row;
                p[0] = v.x; p[APAD] = v.y; p[2 * APAD] = v.z; p[3 * APAD] = v.w;
            }
        }
        layer<200, 100, 4, 20, true, false>(smem, smem + OFF_X, w1, b1,
                                            smem + OFF_H1, nullptr, tid);
        layer<100, 100, 4, 20, true, false>(smem, smem + OFF_H1, w2, b2,
                                            smem + OFF_H1, nullptr, tid);
        layer<100, 200, 7, 10, false, true>(smem, smem + OFF_H1, wl, bl, nullptr,
                                            logits + (size_t)rowBase * D_IN, tid);
        __syncthreads();   // all warps done before s_tile is rewritten
    }
}

// ================== sampler (R12 plateau version, verbatim) ==================
__device__ __forceinline__ void load8(float* dst, const float* src, bool act) {
    if (act) {
        float4 a = *(const float4*)src;
        float4 b = *(const float4*)(src + 4);
        dst[0] = a.x; dst[1] = a.y; dst[2] = a.z; dst[3] = a.w;
        dst[4] = b.x; dst[5] = b.y; dst[6] = b.z; dst[7] = b.w;
    } else {
#pragma unroll
        for (int i = 0; i < 8; i++) dst[i] = 0.5f;
    }
}

__device__ __forceinline__ float gumbel8(float* u, const ull* Epk,
                                         ull C1, ull C2, ull C3, ull M1) {
    constexpr float EPSF = 1.1920929e-07f;
    ull sacc = 0ull;
#pragma unroll
    for (int j = 0; j < 4; j++) {
        float u0 = fmaxf(u[2 * j], EPSF);
        float u1 = fmaxf(u[2 * j + 1], EPSF);
        float l0 = flg2(u0);
        float l1 = flg2(u1);
        ull upk = pack2(u0, u1);
        ull xm = add2(upk, M1);
        ull q = fma2(xm, fma2(xm, C3, C2), C1);
        ull pp = mul2(xm, q);
        float p0, p1;
        unpack2(pp, p0, p1);
        float t0 = (u0 > 0.99f) ? p0 : l0;
        float t1 = (u1 > 0.99f) ? p1 : l1;
        ull tt = pack2(t0, t1);
        ull t2 = mul2(tt, tt);
        float s0, s1;
        unpack2(t2, s0, s1);
        ull rr = pack2(frcp(s0), frcp(s1));
        ull w = mul2(Epk[j], rr);
        float w0, w1;
        unpack2(w, w0, w1);
        u[2 * j] = w0; u[2 * j + 1] = w1;
        sacc = add2(sacc, w);
    }
    float sl, sh;
    unpack2(sacc, sl, sh);
    return sl + sh;
}

__global__ __launch_bounds__(256, 4) void sample_kernel(
    const float* __restrict__ x, const float* __restrict__ uniform,
    const float* __restrict__ logits,
    const float* __restrict__ wo, const float* __restrict__ bo,
    float* __restrict__ preds, float* __restrict__ samples) {
    const int b = (blockIdx.x * 256 + threadIdx.x) >> 5;
    const int lane = threadIdx.x & 31;
    const bool act = lane < 25;
    const int d0 = 8 * lane;

    const ull C1 = pack2(1.44269504f, 1.44269504f);
    const ull C2 = pack2(-0.72134752f, -0.72134752f);
    const ull C3 = pack2(0.48089835f, 0.48089835f);
    const ull M1 = pack2(-1.0f, -1.0f);

    ull Epk[4];
    float smp[8];
    {
        float lg[8];
        if (act) load8(lg, &logits[(size_t)b * D_IN + d0], true);
        else {
#pragma unroll
            for (int i = 0; i < 8; i++) lg[i] = -1e30f;
        }
        float m = lg[0];
#pragma unroll
        for (int i = 1; i < 8; i++) m = fmaxf(m, lg[i]);
#pragma unroll
        for (int off = 16; off > 0; off >>= 1)
            m = fmaxf(m, __shfl_xor_sync(0xffffffffu, m, off));
#pragma unroll
        for (int j = 0; j < 4; j++) {
            float e0 = act ? __expf(2.0f * (lg[2 * j] - m)) : 0.0f;
            float e1 = act ? __expf(2.0f * (lg[2 * j + 1] - m)) : 0.0f;
            Epk[j] = pack2(e0, e1);
        }
#pragma unroll
        for (int i = 0; i < 8; i++) smp[i] = 0.0f;
    }

    const float* up = uniform + (size_t)b * (K_SAMP * D_IN) + d0;
    float ua[8], ub[8];
    load8(ua, up, act);
    load8(ub, up + D_IN, act);

#pragma unroll
    for (int kp = 0; kp < K_SAMP / 2; kp++) {
        float na[8], nb[8];
        if (kp < K_SAMP / 2 - 1) {
            load8(na, up + (2 * kp + 2) * D_IN, act);
            load8(nb, up + (2 * kp + 3) * D_IN, act);
        }
        float sA = gumbel8(ua, Epk, C1, C2, C3, M1);
        float sB = gumbel8(ub, Epk, C1, C2, C3, M1);
#pragma unroll
        for (int off = 16; off > 0; off >>= 1) {
            sA += __shfl_xor_sync(0xffffffffu, sA, off);
            sB += __shfl_xor_sync(0xffffffffu, sB, off);
        }
        float ia = frcp(sA), ib = frcp(sB);
#pragma unroll
        for (int i = 0; i < 8; i++) {
            smp[i] = fmaxf(smp[i], ua[i] * ia);
            smp[i] = fmaxf(smp[i], ub[i] * ib);
        }
        if (kp < K_SAMP / 2 - 1) {
#pragma unroll
            for (int i = 0; i < 8; i++) { ua[i] = na[i]; ub[i] = nb[i]; }
        }
    }

    if (act) {
        *(float4*)&samples[(size_t)b * D_IN + d0] =
            make_float4(smp[0], smp[1], smp[2], smp[3]);
        *(float4*)&samples[(size_t)b * D_IN + d0 + 4] =
            make_float4(smp[4], smp[5], smp[6], smp[7]);
    }

    float p0 = 0.0f, p1 = 0.0f;
    if (act) {
        float xv[8];
        load8(xv, &x[(size_t)b * D_IN + d0], true);
#pragma unroll
        for (int i = 0; i < 8; i += 2) {
            float4 w4 = *(const float4*)&wo[(d0 + i) * 2];
            float a0 = xv[i] * smp[i], a1 = xv[i + 1] * smp[i + 1];
            p0 += a0 * w4.x + a1 * w4.z;
            p1 += a0 * w4.y + a1 * w4.w;
        }
    }
#pragma unroll
    for (int off = 16; off > 0; off >>= 1) {
        p0 += __shfl_xor_sync(0xffffffffu, p0, off);
        p1 += __shfl_xor_sync(0xffffffffu, p1, off);
    }
    if (lane == 0) {
        p0 += bo[0]; p1 += bo[1];
        float mm = fmaxf(p0, p1);
        float e0 = __expf(p0 - mm), e1 = __expf(p1 - mm);
        float is = 1.0f / (e0 + e1);
        preds[(size_t)b * 2 + 0] = e0 * is;
        preds[(size_t)b * 2 + 1] = e1 * is;
    }
}

extern "C" void kernel_launch(void* const* d_in, const int* in_sizes, int n_in,
                              void* d_out, int out_size) {
    const float* x  = (const float*)d_in[0];
    const float* un = (const float*)d_in[1];
    const float* w1 = (const float*)d_in[2];
    const float* b1 = (const float*)d_in[3];
    const float* w2 = (const float*)d_in[4];
    const float* b2 = (const float*)d_in[5];
    const float* wl = (const float*)d_in[6];
    const float* bl = (const float*)d_in[7];
    const float* wo = (const float*)d_in[8];
    const float* bo = (const float*)d_in[9];
    float* out = (float*)d_out;

    float* lgts;
    cudaGetSymbolAddress((void**)&lgts, g_logits);
    unsigned* ctr;
    cudaGetSymbolAddress((void**)&ctr, g_ctr);
    cudaMemsetAsync(ctr, 0, sizeof(unsigned));

    const int smem_bytes = SMEM_FLOATS * (int)sizeof(float);  // 102096
    cudaFuncSetAttribute(mlp_kernel, cudaFuncAttributeMaxDynamicSharedMemorySize, smem_bytes);

    mlp_kernel<<<MLP_GRID, 256, smem_bytes>>>(x, w1, b1, w2, b2, wl, bl, lgts);
    sample_kernel<<<B_ROWS / 8, 256>>>(x, un, lgts, wo, bo,
                                       out, out + (size_t)B_ROWS * 2);
}